// round 10
// baseline (speedup 1.0000x reference)
#include <cuda_runtime.h>
#include <math.h>

#define Bb 4
#define Ssz 2048
#define Dd 1024
#define Hh 16
#define DH 64
#define NBH (Bb*Hh)          // 64
#define BM2 128
#define BN2 64

// Scratch (allocation-free rule: device globals)
__device__ float g_Q[NBH * Ssz * DH];   // [bh][s][d]
__device__ float g_K[NBH * Ssz * DH];   // [bh][s][d]
__device__ float g_Kmean[NBH * DH];

// ---------------------------------------------------------------------------
// Kernel 1: fused QK projection  C = x @ W^T + b, de-interleaved into g_Q/g_K
// 128x128 tile, 8x8 microtile, DOUBLE-BUFFERED smem staging: one sync per
// K-chunk; stores to buf^1 overlap compute on buf.
// ---------------------------------------------------------------------------
__global__ __launch_bounds__(256, 2) void proj_kernel(const float* __restrict__ x,
                                                      const float* __restrict__ W,
                                                      const float* __restrict__ bias) {
    __shared__ float As[2][8][128];   // [buf][k][m]
    __shared__ float Bs[2][8][128];   // [buf][k][n]
    const int m0 = blockIdx.y * 128;
    const int n0 = blockIdx.x * 128;
    const int t  = threadIdx.x;
    const int tx = t & 15, ty = t >> 4;
    const int lr = t >> 1, lk = (t & 1) * 4;

    float acc[8][8];
#pragma unroll
    for (int i = 0; i < 8; i++)
#pragma unroll
        for (int j = 0; j < 8; j++) acc[i][j] = 0.f;

    const float* Ap = x + (m0 + lr) * Dd + lk;
    const float* Bp = W + (n0 + lr) * Dd + lk;

    // prologue: chunk 0 -> buf 0; prefetch chunk 1 into regs
    float4 av = *(const float4*)(Ap);
    float4 bv = *(const float4*)(Bp);
    As[0][lk + 0][lr] = av.x; As[0][lk + 1][lr] = av.y;
    As[0][lk + 2][lr] = av.z; As[0][lk + 3][lr] = av.w;
    Bs[0][lk + 0][lr] = bv.x; Bs[0][lk + 1][lr] = bv.y;
    Bs[0][lk + 2][lr] = bv.z; Bs[0][lk + 3][lr] = bv.w;
    av = *(const float4*)(Ap + 8);
    bv = *(const float4*)(Bp + 8);
    __syncthreads();

    int cur = 0;
    for (int k0 = 0; k0 < Dd; k0 += 8) {
        // stage chunk k0+8 into the other buffer (overlaps compute below)
        if (k0 + 8 < Dd) {
            const int nb = cur ^ 1;
            As[nb][lk + 0][lr] = av.x; As[nb][lk + 1][lr] = av.y;
            As[nb][lk + 2][lr] = av.z; As[nb][lk + 3][lr] = av.w;
            Bs[nb][lk + 0][lr] = bv.x; Bs[nb][lk + 1][lr] = bv.y;
            Bs[nb][lk + 2][lr] = bv.z; Bs[nb][lk + 3][lr] = bv.w;
            if (k0 + 16 < Dd) {
                av = *(const float4*)(Ap + k0 + 16);
                bv = *(const float4*)(Bp + k0 + 16);
            }
        }
#pragma unroll
        for (int k = 0; k < 8; k++) {
            float a[8], bb[8];
            float4 a0 = *(const float4*)&As[cur][k][ty * 4];
            float4 a1 = *(const float4*)&As[cur][k][64 + ty * 4];
            float4 b0 = *(const float4*)&Bs[cur][k][tx * 4];
            float4 b1 = *(const float4*)&Bs[cur][k][64 + tx * 4];
            a[0]=a0.x; a[1]=a0.y; a[2]=a0.z; a[3]=a0.w;
            a[4]=a1.x; a[5]=a1.y; a[6]=a1.z; a[7]=a1.w;
            bb[0]=b0.x; bb[1]=b0.y; bb[2]=b0.z; bb[3]=b0.w;
            bb[4]=b1.x; bb[5]=b1.y; bb[6]=b1.z; bb[7]=b1.w;
#pragma unroll
            for (int i = 0; i < 8; i++)
#pragma unroll
                for (int j = 0; j < 8; j++)
                    acc[i][j] = fmaf(a[i], bb[j], acc[i][j]);
        }
        __syncthreads();
        cur ^= 1;
    }

    // Epilogue: route column n -> (q|k)[b][h][s][d]; n = (h*64+d)*2 + c
#pragma unroll
    for (int i = 0; i < 8; i++) {
        int rr = (i < 4) ? (ty * 4 + i) : (64 + ty * 4 + (i - 4));
        int m = m0 + rr;
        int b = m >> 11;
        int s = m & 2047;
#pragma unroll
        for (int j = 0; j < 8; j++) {
            int cc = (j < 4) ? (tx * 4 + j) : (64 + tx * 4 + (j - 4));
            int n = n0 + cc;
            float v = acc[i][j] + bias[n];
            int c  = n & 1;
            int hd = n >> 1;            // h*64 + d
            int h  = hd >> 6;
            int d  = hd & 63;
            int dst = ((b * Hh + h) * Ssz + s) * DH + d;
            if (c == 0) g_Q[dst] = v; else g_K[dst] = v;
        }
    }
}

// ---------------------------------------------------------------------------
// Kernel 2: k_mean[bh][d] = mean over s of g_K[bh][s][d]
// ---------------------------------------------------------------------------
__global__ __launch_bounds__(256) void kmean_kernel() {
    __shared__ float red[256];
    const int bh = blockIdx.x;
    const int t = threadIdx.x;
    const int d = t & 63, part = t >> 6;
    const float* kp = g_K + bh * (Ssz * DH) + d;
    float s = 0.f;
    for (int j = part; j < Ssz; j += 4) s += kp[j * DH];
    red[t] = s;
    __syncthreads();
    if (part == 0) {
        float tot = red[d] + red[64 + d] + red[128 + d] + red[192 + d];
        g_Kmean[bh * DH + d] = tot * (1.0f / Ssz);
    }
}

// selu(z) with fast exp (MUFU.EX2): error ~1e-7 rel, fine vs 1e-3 gate
__device__ __forceinline__ float selu_z(float z) {
    const float lam = 1.0507009873554805f;
    const float lam_al = 1.7580993408473766f;
    float e = __expf(z);
    return z > 0.f ? lam * z : fmaf(lam_al, e, -lam_al);
}

// ---------------------------------------------------------------------------
// Kernel 3: fused attention.
// Per block: one (b,h) and a 128-row i-tile. Loop j in 64-wide tiles:
//   S = Qs Ks^T ; f = selu(scale*S - mu_row) ; out += f @ V
// mu_row = scale * q_row . k_mean  (algebraic identity for the row mean)
// Next K/V tile prefetched into registers during GEMM2.
// ---------------------------------------------------------------------------
__global__ __launch_bounds__(256) void attn_kernel(const float* __restrict__ x,
                                                   float* __restrict__ out) {
    extern __shared__ float sm[];
    float* Qs = sm;                    // [64][128]   Qs[k*128 + r]
    float* Ks = Qs + 64 * 128;         // [64][68]    Ks[k*68 + c]
    float* Vs = Ks + 64 * 68;          // [64][64]    Vs[c*64 + d]
    float* Ssm = Vs + 64 * 64;         // [64][128]   Ssm[c*128 + r]
    float* mu = Ssm + 64 * 128;        // [128]
    float* km = mu + 128;              // [64]

    const int blk = blockIdx.x;
    const int bh = blk >> 4;           // 0..63
    const int it = blk & 15;
    const int b = bh >> 4, h = bh & 15;
    const int i0 = it * BM2;
    const int t = threadIdx.x;
    const int tx = t & 15, ty = t >> 4;

    // Load Q tile transposed: g_Q[bh][i0+r][k] -> Qs[k][r]
    {
        const float* qg = g_Q + (bh * Ssz + i0) * DH;
#pragma unroll
        for (int p = 0; p < 8; p++) {
            int idx = p * 256 + t;          // float4 index 0..2047
            int r = idx >> 4;               // 0..127
            int kq = (idx & 15) * 4;        // 0..60
            float4 v = *(const float4*)(qg + r * DH + kq);
            Qs[(kq + 0) * 128 + r] = v.x;
            Qs[(kq + 1) * 128 + r] = v.y;
            Qs[(kq + 2) * 128 + r] = v.z;
            Qs[(kq + 3) * 128 + r] = v.w;
        }
    }
    if (t < 64) km[t] = g_Kmean[bh * DH + t];
    __syncthreads();

    if (t < 128) {
        float s = 0.f;
#pragma unroll
        for (int k = 0; k < 64; k++) s = fmaf(Qs[k * 128 + t], km[k], s);
        mu[t] = s * 0.125f;                // scale = dh^-0.5 = 0.125
    }
    __syncthreads();

    float oacc[8][4];
#pragma unroll
    for (int i = 0; i < 8; i++)
#pragma unroll
        for (int j = 0; j < 4; j++) oacc[i][j] = 0.f;

    const float* xg = x + (b * Ssz) * Dd + h * DH;    // V[j][d] = xg[j*Dd + d]
    const float* kg = g_K + bh * (Ssz * DH);

    // register prefetch of first K/V tile (4 float4 each)
    float4 pk[4], pv[4];
#pragma unroll
    for (int p = 0; p < 4; p++) {
        int idx = p * 256 + t;
        int c = idx >> 4;
        int kq = (idx & 15) * 4;
        pk[p] = *(const float4*)(kg + c * DH + kq);
        pv[p] = *(const float4*)(xg + c * Dd + kq);
    }

    for (int j0 = 0; j0 < Ssz; j0 += BN2) {
        __syncthreads();   // WAR: previous iter's GEMM2 readers done
        // Store prefetched K (transposed) and V tiles
#pragma unroll
        for (int p = 0; p < 4; p++) {
            int idx = p * 256 + t;
            int c = idx >> 4;
            int kq = (idx & 15) * 4;
            Ks[(kq + 0) * 68 + c] = pk[p].x;
            Ks[(kq + 1) * 68 + c] = pk[p].y;
            Ks[(kq + 2) * 68 + c] = pk[p].z;
            Ks[(kq + 3) * 68 + c] = pk[p].w;
            *(float4*)&Vs[c * 64 + kq] = pv[p];
        }
        __syncthreads();

        // S-compute: thread owns rows {tx*4+i, 64+tx*4+i}, cols {ty*4+j}
        float sv[8][4];
#pragma unroll
        for (int i = 0; i < 8; i++)
#pragma unroll
            for (int j = 0; j < 4; j++) sv[i][j] = 0.f;
#pragma unroll
        for (int k = 0; k < 64; k++) {
            float4 q0 = *(const float4*)&Qs[k * 128 + tx * 4];
            float4 q1 = *(const float4*)&Qs[k * 128 + 64 + tx * 4];
            float4 kk = *(const float4*)&Ks[k * 68 + ty * 4];
            float qa[8] = {q0.x, q0.y, q0.z, q0.w, q1.x, q1.y, q1.z, q1.w};
            float kb[4] = {kk.x, kk.y, kk.z, kk.w};
#pragma unroll
            for (int i = 0; i < 8; i++)
#pragma unroll
                for (int j = 0; j < 4; j++)
                    sv[i][j] = fmaf(qa[i], kb[j], sv[i][j]);
        }
        // selu(scale*s - mu)
#pragma unroll
        for (int i = 0; i < 8; i++) {
            int r = (i < 4) ? (tx * 4 + i) : (64 + tx * 4 + (i - 4));
            float m_ = mu[r];
#pragma unroll
            for (int j = 0; j < 4; j++) {
                float z = fmaf(sv[i][j], 0.125f, -m_);
                sv[i][j] = selu_z(z);
            }
        }
        // Write S tile
#pragma unroll
        for (int j = 0; j < 4; j++) {
            int c = ty * 4 + j;
            *(float4*)&Ssm[c * 128 + tx * 4] =
                make_float4(sv[0][j], sv[1][j], sv[2][j], sv[3][j]);
            *(float4*)&Ssm[c * 128 + 64 + tx * 4] =
                make_float4(sv[4][j], sv[5][j], sv[6][j], sv[7][j]);
        }

        // Prefetch next tile's K/V into registers (sv is dead now);
        // these LDGs overlap the Ssm sync + GEMM2 below.
        {
            int jn = (j0 + BN2 < Ssz) ? j0 + BN2 : 0;
            const float* kgn = kg + jn * DH;
            const float* xgn = xg + jn * Dd;
#pragma unroll
            for (int p = 0; p < 4; p++) {
                int idx = p * 256 + t;
                int c = idx >> 4;
                int kq = (idx & 15) * 4;
                pk[p] = *(const float4*)(kgn + c * DH + kq);
                pv[p] = *(const float4*)(xgn + c * Dd + kq);
            }
        }
        __syncthreads();

        // GEMM2: out[r][d] += S[r][c] * V[c][d]; rows {ty*4+i, 64+ty*4+i}, d {tx*4+j}
#pragma unroll
        for (int c = 0; c < 64; c++) {
            float4 s0 = *(const float4*)&Ssm[c * 128 + ty * 4];
            float4 s1 = *(const float4*)&Ssm[c * 128 + 64 + ty * 4];
            float4 vv = *(const float4*)&Vs[c * 64 + tx * 4];
            float sa[8] = {s0.x, s0.y, s0.z, s0.w, s1.x, s1.y, s1.z, s1.w};
            float vb[4] = {vv.x, vv.y, vv.z, vv.w};
#pragma unroll
            for (int i = 0; i < 8; i++)
#pragma unroll
                for (int j = 0; j < 4; j++)
                    oacc[i][j] = fmaf(sa[i], vb[j], oacc[i][j]);
        }
    }

    // Epilogue: out[b][i0+r][h*64 + d] = oacc * S^-0.5
    const float os = 0.022097086912079608f;   // 1/sqrt(2048)
    float* og = out + (b * Ssz + i0) * Dd + h * DH;
#pragma unroll
    for (int i = 0; i < 8; i++) {
        int r = (i < 4) ? (ty * 4 + i) : (64 + ty * 4 + (i - 4));
        float4 v = make_float4(oacc[i][0] * os, oacc[i][1] * os,
                               oacc[i][2] * os, oacc[i][3] * os);
        *(float4*)(og + r * Dd + tx * 4) = v;
    }
}

// ---------------------------------------------------------------------------
extern "C" void kernel_launch(void* const* d_in, const int* in_sizes, int n_in,
                              void* d_out, int out_size) {
    const float* x    = (const float*)d_in[0];
    const float* W    = (const float*)d_in[1];
    const float* bias = (const float*)d_in[2];
    float* out = (float*)d_out;

    const int ATTN_SMEM = (64 * 128 + 64 * 68 + 64 * 64 + 64 * 128 + 128 + 64) *
                          (int)sizeof(float);   // 100096 B
    cudaFuncSetAttribute(attn_kernel, cudaFuncAttributeMaxDynamicSharedMemorySize,
                         ATTN_SMEM);

    proj_kernel<<<dim3(16, 64), 256>>>(x, W, bias);
    kmean_kernel<<<NBH, 256>>>();
    attn_kernel<<<NBH * (Ssz / BM2), 256, ATTN_SMEM>>>(x, out);
}